// round 2
// baseline (speedup 1.0000x reference)
#include <cuda_runtime.h>

// Fused stream-mix kernel:
//   out[bs, i, d] = (sum_j h_res[bs, i, j] * x[bs, j, d]) * h_out[bs, d]
//                   + h_post[bs, i] * x[bs, i, d]
// Shapes (flattened over b,s): x [BS, 4, 1024], h_res [BS, 4, 4],
// h_out [BS, 1024], h_post [BS, 4], out [BS, 4, 1024].
//
// HBM-bound: ~578 MB total traffic. One block per token, 256 threads,
// one float4 column (4 d's) per thread across all 4 streams.

constexpr int N_STREAMS = 4;
constexpr int D_MODEL   = 1024;
constexpr int D4        = D_MODEL / 4;   // 256 float4 columns

__global__ __launch_bounds__(D4, 4)
void fused_stream_mix_kernel(const float* __restrict__ x,
                             const float* __restrict__ h_res,
                             const float* __restrict__ h_out,
                             const float* __restrict__ h_post,
                             float* __restrict__ out) {
    const long long bs = blockIdx.x;          // token index in [0, B*S)
    const int t = threadIdx.x;                // float4 column in [0, 256)

    // Broadcast loads: every thread reads the same 16+4 scalars (L1 broadcast).
    const float* hr = h_res + bs * (N_STREAMS * N_STREAMS);
    const float* hp = h_post + bs * N_STREAMS;

    const float r00 = hr[0],  r01 = hr[1],  r02 = hr[2],  r03 = hr[3];
    const float r10 = hr[4],  r11 = hr[5],  r12 = hr[6],  r13 = hr[7];
    const float r20 = hr[8],  r21 = hr[9],  r22 = hr[10], r23 = hr[11];
    const float r30 = hr[12], r31 = hr[13], r32 = hr[14], r33 = hr[15];
    const float p0 = hp[0], p1 = hp[1], p2 = hp[2], p3 = hp[3];

    // Front-batched wide loads: 5 independent float4's in flight (MLP=5).
    const float4* xp  = reinterpret_cast<const float4*>(x + bs * (long long)(N_STREAMS * D_MODEL));
    const float4* hop = reinterpret_cast<const float4*>(h_out + bs * (long long)D_MODEL);

    const float4 x0 = xp[0 * D4 + t];
    const float4 x1 = xp[1 * D4 + t];
    const float4 x2 = xp[2 * D4 + t];
    const float4 x3 = xp[3 * D4 + t];
    const float4 ho = hop[t];

    float4 o0, o1, o2, o3;

    o0.x = fmaf(r00, x0.x, fmaf(r01, x1.x, fmaf(r02, x2.x, r03 * x3.x))) * ho.x + p0 * x0.x;
    o0.y = fmaf(r00, x0.y, fmaf(r01, x1.y, fmaf(r02, x2.y, r03 * x3.y))) * ho.y + p0 * x0.y;
    o0.z = fmaf(r00, x0.z, fmaf(r01, x1.z, fmaf(r02, x2.z, r03 * x3.z))) * ho.z + p0 * x0.z;
    o0.w = fmaf(r00, x0.w, fmaf(r01, x1.w, fmaf(r02, x2.w, r03 * x3.w))) * ho.w + p0 * x0.w;

    o1.x = fmaf(r10, x0.x, fmaf(r11, x1.x, fmaf(r12, x2.x, r13 * x3.x))) * ho.x + p1 * x1.x;
    o1.y = fmaf(r10, x0.y, fmaf(r11, x1.y, fmaf(r12, x2.y, r13 * x3.y))) * ho.y + p1 * x1.y;
    o1.z = fmaf(r10, x0.z, fmaf(r11, x1.z, fmaf(r12, x2.z, r13 * x3.z))) * ho.z + p1 * x1.z;
    o1.w = fmaf(r10, x0.w, fmaf(r11, x1.w, fmaf(r12, x2.w, r13 * x3.w))) * ho.w + p1 * x1.w;

    o2.x = fmaf(r20, x0.x, fmaf(r21, x1.x, fmaf(r22, x2.x, r23 * x3.x))) * ho.x + p2 * x2.x;
    o2.y = fmaf(r20, x0.y, fmaf(r21, x1.y, fmaf(r22, x2.y, r23 * x3.y))) * ho.y + p2 * x2.y;
    o2.z = fmaf(r20, x0.z, fmaf(r21, x1.z, fmaf(r22, x2.z, r23 * x3.z))) * ho.z + p2 * x2.z;
    o2.w = fmaf(r20, x0.w, fmaf(r21, x1.w, fmaf(r22, x2.w, r23 * x3.w))) * ho.w + p2 * x2.w;

    o3.x = fmaf(r30, x0.x, fmaf(r31, x1.x, fmaf(r32, x2.x, r33 * x3.x))) * ho.x + p3 * x3.x;
    o3.y = fmaf(r30, x0.y, fmaf(r31, x1.y, fmaf(r32, x2.y, r33 * x3.y))) * ho.y + p3 * x3.y;
    o3.z = fmaf(r30, x0.z, fmaf(r31, x1.z, fmaf(r32, x2.z, r33 * x3.z))) * ho.z + p3 * x3.z;
    o3.w = fmaf(r30, x0.w, fmaf(r31, x1.w, fmaf(r32, x2.w, r33 * x3.w))) * ho.w + p3 * x3.w;

    float4* op = reinterpret_cast<float4*>(out + bs * (long long)(N_STREAMS * D_MODEL));
    op[0 * D4 + t] = o0;
    op[1 * D4 + t] = o1;
    op[2 * D4 + t] = o2;
    op[3 * D4 + t] = o3;
}

extern "C" void kernel_launch(void* const* d_in, const int* in_sizes, int n_in,
                              void* d_out, int out_size) {
    const float* x      = (const float*)d_in[0];  // [B,S,N,D]
    const float* h_res  = (const float*)d_in[1];  // [B,S,N,N]
    const float* h_out  = (const float*)d_in[2];  // [B,S,D]
    const float* h_post = (const float*)d_in[3];  // [B,S,N]
    float* out = (float*)d_out;

    // Number of tokens from h_res element count (BS * N * N).
    const int BS = in_sizes[1] / (N_STREAMS * N_STREAMS);

    fused_stream_mix_kernel<<<BS, D4>>>(x, h_res, h_out, h_post, out);
}